// round 16
// baseline (speedup 1.0000x reference)
#include <cuda_runtime.h>
#include <math.h>

#define NFACES 512
#define NVERTS 642
#define HW     256
#define NPIX   (HW*HW)
#define TILE   8
#define TPD    32                 // tiles per dimension
#define RBLK   (TPD*TPD)          // 1024 blocks
#define RTPB   256                // 8 warps; phase2: 8 groups x 32 lanes x 2px

__device__ float    g_partials[RBLK];
__device__ unsigned g_counter;          // zero at load; wraps each replay

// ---- packed f32x2 helpers (Blackwell) --------------------------------------
__device__ __forceinline__ unsigned long long pk2(float lo, float hi) {
    unsigned long long r;
    asm("mov.b64 %0, {%1, %2};" : "=l"(r) : "f"(lo), "f"(hi));
    return r;
}
__device__ __forceinline__ void upk2(unsigned long long v, float& lo, float& hi) {
    asm("mov.b64 {%0, %1}, %2;" : "=f"(lo), "=f"(hi) : "l"(v));
}
__device__ __forceinline__ unsigned long long fma2(unsigned long long a,
                                                   unsigned long long b,
                                                   unsigned long long c) {
    unsigned long long d;
    asm("fma.rn.f32x2 %0, %1, %2, %3;" : "=l"(d) : "l"(a), "l"(b), "l"(c));
    return d;
}

// ---------------------------------------------------------------------------
__global__ void __launch_bounds__(RTPB, 6) render(const float* __restrict__ verts,
                                                  const int*   __restrict__ faces,
                                                  const float* __restrict__ tex,
                                                  const float* __restrict__ ref,
                                                  float*       __restrict__ out) {
    __shared__ float4 sQ[NFACES*3];     // 24 KB survivor coefficients (pair layout)
    __shared__ short  sList[NFACES];    // survivor -> original face id
    __shared__ float4 sU[NVERTS];       // union: verts (phase1) / sBd,sLi (phase2+)
    __shared__ int    sCnt;
    __shared__ float  sWsum[8];

    float (*sBd)[64] = reinterpret_cast<float(*)[64]>(sU);                 // 2KB
    short (*sLi)[64] = reinterpret_cast<short(*)[64]>((char*)sU + 2048);   // 1KB

    const int tid  = threadIdx.x;
    const int bid  = blockIdx.x;
    const int lane = tid & 31, w = tid >> 5;

    // Tile geometry
    const int tileX = bid & (TPD-1), tileY = bid / TPD;
    const int c0 = tileX * TILE, r0 = tileY * TILE;
    const float SC = 2.0f / 256.0f;
    const float xc = (c0 + 4.0f) * SC - 1.0f;
    const float yc = 1.0f - (r0 + 4.0f) * SC;
    const float hx = 3.5f * SC, hy = 3.5f * SC;
    const float tXmin = xc - hx - 1e-6f, tXmax = xc + hx + 1e-6f;
    const float tYmin = yc - hy - 1e-6f, tYmax = yc + hy + 1e-6f;

    // Camera basis — compile-time constant-folded
    const float ex = 2.732f, ey = 0.0f, ez = -1.6728675276352844e-16f;
    const float nrm = sqrtf(ex*ex + ey*ey + ez*ez);
    const float zx = -ex/nrm, zy = -ey/nrm, zz = -ez/nrm;
    float xxu = zz, xyu = 0.f, xzu = -zx;
    const float xn = sqrtf(xxu*xxu + xyu*xyu + xzu*xzu);
    const float xx = xxu/xn, xy = xyu/xn, xz = xzu/xn;
    const float yx = zy*xz - zz*xy;
    const float yy = zz*xx - zx*xz;
    const float yz = zx*xy - zy*xx;

    if (tid == 0) sCnt = 0;

    // ========== Stage transformed vertices into SMEM ========================
    for (int v = tid; v < NVERTS; v += RTPB) {
        float vx = __ldg(&verts[3*v+0]) - ex;
        float vy = __ldg(&verts[3*v+1]) - ey;
        float vz = __ldg(&verts[3*v+2]) - ez;
        float X = vx*xx + vy*xy + vz*xz;
        float Y = vx*yx + vy*yy + vz*yz;
        float Z = vx*zx + vy*zy + vz*zz;
        sU[v] = make_float4(X, Y, Z, 0.f);
    }
    __syncthreads();

    // ========== Fused prep + exact SAT cull, atomic compaction ==============
    #pragma unroll
    for (int base = 0; base < NFACES; base += RTPB) {
        int f = base + tid;
        int i0 = __ldg(&faces[3*f+0]);
        int i1 = __ldg(&faces[3*f+1]);
        int i2 = __ldg(&faces[3*f+2]);

        float4 A = sU[i0];
        float4 B = sU[i1];
        float4 C = sU[i2];
        float ax = A.x, ay = A.y, az = A.z;
        float bx = B.x, by = B.y, bz = B.z;
        float cx = C.x, cy = C.y, cz = C.z;

        float denom = (bx-ax)*(cy-ay) - (by-ay)*(cx-ax);
        bool nondeg = fabsf(denom) > 1e-8f;
        float s = (denom > 0.f) ? 1.f : -1.f;

        float A0 = s*(by-cy), B0 = s*(cx-bx), C0 = s*((cy-by)*bx - (cx-bx)*by);
        float A1 = s*(cy-ay), B1 = s*(ax-cx), C1 = s*((ay-cy)*cx - (ax-cx)*cy);
        float A2 = s*(ay-by), B2 = s*(bx-ax), C2 = s*((by-ay)*ax - (bx-ax)*ay);

        // SAT axis set 1: triangle edge normals (conservative max over hull)
        float u0m = fmaf(A0, xc, fmaf(B0, yc, C0)) + fabsf(A0)*hx + fabsf(B0)*hy;
        float u1m = fmaf(A1, xc, fmaf(B1, yc, C1)) + fabsf(A1)*hx + fabsf(B1)*hy;
        float u2m = fmaf(A2, xc, fmaf(B2, yc, C2)) + fabsf(A2)*hx + fabsf(B2)*hy;
        // SAT axis set 2: box axes (triangle bbox vs padded tile hull)
        float xmn = fminf(ax, fminf(bx, cx));
        float xmx = fmaxf(ax, fmaxf(bx, cx));
        float ymn = fminf(ay, fminf(by, cy));
        float ymx = fmaxf(ay, fmaxf(by, cy));
        bool ov = nondeg
                & (u0m >= -1e-5f) & (u1m >= -1e-5f) & (u2m >= -1e-5f)
                & (xmn <= tXmax) & (xmx >= tXmin)
                & (ymn <= tYmax) & (ymx >= tYmin);

        unsigned m = __ballot_sync(0xFFFFFFFFu, ov);
        int wbase = 0;
        if (lane == 0 && m) wbase = atomicAdd(&sCnt, __popc(m));
        wbase = __shfl_sync(0xFFFFFFFFu, wbase, 0);
        if (ov) {
            // survivor-only: reciprocal + depth plane
            float r  = 1.0f / fabsf(denom);
            float D0 = az*r, D1 = bz*r, D2 = cz*r;
            float Dx = A0*D0 + A1*D1 + A2*D2;
            float Dy = B0*D0 + B1*D1 + B2*D2;
            float Dc = C0*D0 + C1*D1 + C2*D2;
            int pos = wbase + __popc(m & ((1u << lane) - 1u));
            sList[pos] = (short)f;
            // pair-aligned layout for f32x2:
            sQ[pos*3+0] = make_float4(A0, A1, B0, B1);   // (A0,A1)|(B0,B1)
            sQ[pos*3+1] = make_float4(C0, C1, A2, Dx);   // (C0,C1)|(A2,Dx)
            sQ[pos*3+2] = make_float4(B2, Dy, C2, Dc);   // (B2,Dy)|(C2,Dc)
        }
    }
    __syncthreads();
    const int nf = sCnt;

    // ========== Phase 2: 8 warp-groups, 2 px/thread, packed f32x2 ===========
    const int pcol = (lane & 3) << 1;
    const int prow = lane >> 2;
    const float px = (c0 + pcol + 0.5f) * SC - 1.0f;
    const float py = 1.0f - (r0 + prow + 0.5f) * SC;

    const unsigned long long pxx = pk2(px, px);
    const unsigned long long pyy = pk2(py, py);
    const unsigned long long scc = pk2(SC, SC);

    const int fBeg = (nf * w)     >> 3;
    const int fEnd = (nf * (w+1)) >> 3;

    float bd0 = __int_as_float(0x7f800000), bd1 = bd0;
    int   li0 = -1, li1 = -1;

    const ulonglong2* sQ2 = reinterpret_cast<const ulonglong2*>(sQ);

    #pragma unroll 4
    for (int i = fBeg; i < fEnd; i++) {
        ulonglong2 qa = sQ2[i*3+0];   // (A0,A1) | (B0,B1)
        ulonglong2 qb = sQ2[i*3+1];   // (C0,C1) | (A2,Dx)
        ulonglong2 qc = sQ2[i*3+2];   // (B2,Dy) | (C2,Dc)
        unsigned long long u01 = fma2(qa.x, pxx, fma2(qa.y, pyy, qb.x)); // (u0,u1)
        unsigned long long u2d = fma2(qb.y, pxx, fma2(qc.x, pyy, qc.y)); // (u2,d)
        float u0, u1, u2, d;
        upk2(u01, u0, u1); upk2(u2d, u2, d);
        float m0 = fminf(u0, fminf(u1, u2));
        if (m0 >= 0.f && d < bd0) { bd0 = d; li0 = i; }
        // pixel+1: u0+=A0*SC, u1+=A1*SC, u2+=A2*SC, d+=Dx*SC
        u01 = fma2(qa.x, scc, u01);
        u2d = fma2(qb.y, scc, u2d);
        upk2(u01, u0, u1); upk2(u2d, u2, d);
        float m1 = fminf(u0, fminf(u1, u2));
        if (m1 >= 0.f && d < bd1) { bd1 = d; li1 = i; }
    }
    __syncthreads();                 // sU reads done; reuse as sBd/sLi
    {
        int sub = prow * 8 + pcol;
        sBd[w][sub]   = bd0;  sLi[w][sub]   = (short)li0;
        sBd[w][sub+1] = bd1;  sLi[w][sub+1] = (short)li1;
    }
    __syncthreads();

    // ========== Epilogue: merge 8 candidates + shade + SSE ==================
    float acc = 0.f;
    if (tid < 64) {
        float best = sBd[0][tid];
        int   bli  = sLi[0][tid];
        #pragma unroll
        for (int g = 1; g < 8; g++) {
            float dg = sBd[g][tid];
            if (dg < best) { best = dg; bli = sLi[g][tid]; }   // ascending group = argmin
        }
        const float qx = (c0 + (tid & 7) + 0.5f) * SC - 1.0f;
        const float qy = 1.0f - (r0 + (tid >> 3) + 0.5f) * SC;
        const int   p  = (r0 + (tid >> 3)) * HW + (c0 + (tid & 7));

        float cc0 = 0.f, cc1 = 0.f, cc2 = 0.f;
        if (bli >= 0) {
            int fo = sList[bli];
            float4 qa = sQ[bli*3+0];   // A0 A1 B0 B1
            float4 qb = sQ[bli*3+1];   // C0 C1 A2 Dx
            float4 qc = sQ[bli*3+2];   // B2 Dy C2 Dc
            float u0 = fmaf(qa.x, qx, fmaf(qa.z, qy, qb.x));
            float u1 = fmaf(qa.y, qx, fmaf(qa.w, qy, qb.y));
            float u2 = fmaf(qb.z, qx, fmaf(qc.x, qy, qc.z));
            float r  = 1.0f / (u0 + u1 + u2);      // == 1/|denom| (barycentric sum)
            int t0 = min(max((int)rintf(u0 * r * 3.0f), 0), 3);
            int t1 = min(max((int)rintf(u1 * r * 3.0f), 0), 3);
            int t2 = min(max((int)rintf(u2 * r * 3.0f), 0), 3);
            int base = fo*192 + t0*48 + t1*12 + t2*3;
            cc0 = tanhf(__ldg(tex + base + 0));
            cc1 = tanhf(__ldg(tex + base + 1));
            cc2 = tanhf(__ldg(tex + base + 2));
        }
        float e0 = cc0 - __ldg(ref + p);
        float e1 = cc1 - __ldg(ref + p + NPIX);
        float e2 = cc2 - __ldg(ref + p + 2*NPIX);
        acc = fmaf(e0, e0, fmaf(e1, e1, e2*e2));
    }

    // ========== Block + grid reduction ======================================
    #pragma unroll
    for (int o = 16; o > 0; o >>= 1)
        acc += __shfl_down_sync(0xFFFFFFFFu, acc, o);
    if (lane == 0) sWsum[w] = acc;
    __syncthreads();

    __shared__ bool sLast;
    if (tid == 0) {
        g_partials[bid] = sWsum[0] + sWsum[1];
        __threadfence();
        unsigned t = atomicInc(&g_counter, RBLK - 1);   // wraps each replay
        sLast = (t == RBLK - 1);
    }
    __syncthreads();
    if (sLast) {
        float v = __ldcg(&g_partials[tid])
                + __ldcg(&g_partials[tid + 256])
                + __ldcg(&g_partials[tid + 512])
                + __ldcg(&g_partials[tid + 768]);
        #pragma unroll
        for (int o = 16; o > 0; o >>= 1)
            v += __shfl_down_sync(0xFFFFFFFFu, v, o);
        if (lane == 0) sWsum[w] = v;
        __syncthreads();
        if (tid == 0) {
            float s = 0.f;
            #pragma unroll
            for (int i = 0; i < 8; i++) s += sWsum[i];
            out[0] = s;
        }
    }
}

// ---------------------------------------------------------------------------
extern "C" void kernel_launch(void* const* d_in, const int* in_sizes, int n_in,
                              void* d_out, int out_size) {
    const float* verts = nullptr;
    const float* tex   = nullptr;
    const float* ref   = nullptr;
    const int*   faces = nullptr;
    for (int i = 0; i < n_in; i++) {
        switch (in_sizes[i]) {
            case 1926:   verts = (const float*)d_in[i]; break;
            case 98304:  tex   = (const float*)d_in[i]; break;
            case 196608: ref   = (const float*)d_in[i]; break;
            case 1536:   faces = (const int*)  d_in[i]; break;
            default: break;
        }
    }
    render<<<RBLK, RTPB>>>(verts, faces, tex, ref, (float*)d_out);
}